// round 13
// baseline (speedup 1.0000x reference)
#include <cuda_runtime.h>
#include <cuda_fp16.h>
#include <math.h>
#include <stdint.h>

typedef unsigned long long ull;

#define NQ      10
#define KDIM    4096
#define NDIM    1024
#define BM      128
#define BN      256
#define KC      64
#define NCHUNK  64
#define THREADS 544
#define NBLK    (NDIM / BN)          // 4

#if defined(__CUDA_ARCH__) && defined(__CUDA_ARCH_HAS_FEATURE__)
#  if __CUDA_ARCH_HAS_FEATURE__(SM103_ALL) || __CUDA_ARCH_HAS_FEATURE__(SM100_ALL)
#    define TC_OK 1
#  endif
#endif
#ifndef TC_OK
#  define TC_OK 0
#endif

// control SMEM
#define OFF_TMEM 0
#define OFF_M1D  16                  // 2 x 8B mma1-done
#define OFF_CV   32                  // 2 x 8B convert-done (count 16)
#define OFF_MD   48                  // 2 x 8B mma2-done
#define OFF_BF   64                  // 5 x 8B B-slot-full
#define OFF_W1F  104                 // 4 x 8B W1-slot-full
#define OFF_RC   136                 // 5 x 8B B-slot-ready (count 2, cluster)
#define OFF_RW   176                 // 4 x 8B W1-slot-ready (count 2, cluster)
#define OFF_Q    1024                // Q tile 16KB (128 x 128B SW128)
#define OFF_W1S  17408               // 4 x 8KB W1 fp16 tiles
#define OFF_B    50176               // 5 x 32KB W2 fp16 tiles
#define B_SLOT   32768
#define W1_SLOT  8192
#define SMEM_BYTES (OFF_B + 5 * B_SLOT)   // 214016

// TMEM columns
#define TM_D   0                     // main accum, 256 cols
#define TM_D2  256                   // MMA1 out, 2 x 64 cols
#define TM_A   384                   // A operand, 2 x 32 cols

// idesc kind::f16 fp16 in, f32 accum
#define IDESC2 0x08400010u           // M=128, N=256
#define IDESC1 0x08100010u           // M=128, N=64
#define SW128(o) ((o) ^ (((o) >> 3) & 0x70))

// converted W2: [nb][chunk] 32KB fp16 SW128 tiles (8MB)
__device__ __align__(1024) unsigned char g_w2conv[(size_t)NBLK * NCHUNK * B_SLOT];
// converted W1: [chunk] 8KB fp16 SW128 tiles (64 rows(k) x 16 cols(j), padded)
__device__ __align__(1024) unsigned char g_w1conv[(size_t)NCHUNK * W1_SLOT];

static __device__ __forceinline__ uint32_t pack_f16(float lo, float hi) {
    uint32_t r;
    asm("cvt.rn.f16x2.f32 %0, %1, %2;" : "=r"(r) : "f"(hi), "f"(lo));
    return r;
}

// ============================================================================
// Kernel 0: W2 fp32 -> fp16 SW128 tiles
// ============================================================================
__global__ __launch_bounds__(256)
void convert_w2_kernel(const float* __restrict__ W2)
{
    const int t   = blockIdx.x * 256 + threadIdx.x;
    const int row = t >> 9;
    const int k0  = (t & 511) << 3;
    const int nb  = row >> 8, n = row & 255;
    const int c   = k0 >> 6,  k = k0 & 63;

    const float4* p = (const float4*)(W2 + (size_t)row * KDIM + k0);
    const float4 u = p[0], v = p[1];
    uint32_t h0 = pack_f16(u.x, u.y);
    uint32_t h1 = pack_f16(u.z, u.w);
    uint32_t h2 = pack_f16(v.x, v.y);
    uint32_t h3 = pack_f16(v.z, v.w);

    unsigned char* base = g_w2conv + ((size_t)(nb * NCHUNK + c)) * B_SLOT;
    const uint32_t off = SW128((uint32_t)(n * 128 + k * 2));
    *(uint4*)(base + off) = make_uint4(h0, h1, h2, h3);
}

// ============================================================================
// Kernel 1: W1 fp32 -> fp16 SW128 tiles (MMA1 B operand)
// ============================================================================
__global__ __launch_bounds__(256)
void convert_w1_kernel(const float* __restrict__ W1)
{
    const int t = blockIdx.x * 256 + threadIdx.x;    // 4096 threads
    const int chunk = t >> 6, n = t & 63;

    const float* wr = W1 + (size_t)(chunk * KC + n) * NQ;
    uint32_t u0 = pack_f16(wr[0], wr[1]);
    uint32_t u1 = pack_f16(wr[2], wr[3]);
    uint32_t u2 = pack_f16(wr[4], wr[5]);
    uint32_t u3 = pack_f16(wr[6], wr[7]);
    uint32_t u4 = pack_f16(wr[8], wr[9]);

    unsigned char* base = g_w1conv + (size_t)chunk * W1_SLOT;
    *(uint4*)(base + SW128((uint32_t)(n * 128)))      = make_uint4(u0, u1, u2, u3);
    *(uint4*)(base + SW128((uint32_t)(n * 128 + 16))) = make_uint4(u4, 0, 0, 0);
#pragma unroll
    for (int g = 2; g < 8; ++g)
        *(uint4*)(base + SW128((uint32_t)(n * 128 + g * 16))) = make_uint4(0, 0, 0, 0);
}

// ============================================================================
// Kernel 2: tcgen05 double-GEMM with cluster-2 multicast B/W1 supply
// ============================================================================
#if TC_OK
static __device__ __forceinline__ uint32_t smem_u32(const void* p) {
    uint32_t a;
    asm("{ .reg .u64 t; cvta.to.shared.u64 t, %1; cvt.u32.u64 %0, t; }" : "=r"(a) : "l"(p));
    return a;
}
static __device__ __forceinline__ uint32_t cl_rank() {
    uint32_t r;
    asm("mov.u32 %0, %%cluster_ctarank;" : "=r"(r));
    return r;
}
static __device__ __forceinline__ bool elect_one() {
    uint32_t p;
    asm volatile("{ .reg .pred P; elect.sync _|P, 0xFFFFFFFF; selp.b32 %0, 1, 0, P; }" : "=r"(p));
    return p != 0;
}
static __device__ __forceinline__ ull make_desc(uint32_t addr) {  // SW128 K-major
    return (2ULL << 61) | (1ULL << 46) | (64ULL << 32) | (1ULL << 16) |
           (ull)((addr >> 4) & 0x3FFF);
}
static __device__ __forceinline__ void mbar_wait(uint32_t mbar, uint32_t ph) {
    asm volatile(
        "{\n\t.reg .pred P;\n"
        "WL_%=:\n\t"
        "mbarrier.try_wait.parity.acquire.cta.shared::cta.b64 P, [%0], %1, 0x989680;\n\t"
        "@P bra WD_%=;\n\t"
        "bra WL_%=;\n"
        "WD_%=:\n\t}"
        :: "r"(mbar), "r"(ph) : "memory");
}
static __device__ __forceinline__ void mbar_arrive(uint32_t mbar) {
    asm volatile("mbarrier.arrive.shared.b64 _, [%0];" :: "r"(mbar) : "memory");
}
static __device__ __forceinline__ void mbar_arrive_remote(uint32_t mbar, uint32_t target_rank) {
    asm volatile(
        "{\n\t.reg .b32 ra;\n\t"
        "mapa.shared::cluster.u32 ra, %0, %1;\n\t"
        "mbarrier.arrive.shared::cluster.b64 _, [ra];\n\t}"
        :: "r"(mbar), "r"(target_rank) : "memory");
}
static __device__ __forceinline__ void mma_ss(uint32_t d, ull a, ull b, uint32_t idesc, uint32_t en) {
    asm volatile(
        "{\n\t.reg .pred p;\n\t"
        "setp.ne.u32 p, %5, 0;\n\t"
        "tcgen05.mma.cta_group::1.kind::f16 [%0], %1, %2, %3, {%4,%4,%4,%4}, p;\n\t}"
        :: "r"(d), "l"(a), "l"(b), "r"(idesc), "r"(0u), "r"(en) : "memory");
}
static __device__ __forceinline__ void mma_ts(uint32_t d, uint32_t a, ull b, uint32_t idesc, uint32_t en) {
    asm volatile(
        "{\n\t.reg .pred p;\n\t"
        "setp.ne.u32 p, %5, 0;\n\t"
        "tcgen05.mma.cta_group::1.kind::f16 [%0], [%1], %2, %3, {%4,%4,%4,%4}, p;\n\t}"
        :: "r"(d), "r"(a), "l"(b), "r"(idesc), "r"(0u), "r"(en) : "memory");
}
static __device__ __forceinline__ void bulk_copy_mc(uint32_t dst, const void* src,
                                                    uint32_t bytes, uint32_t mbar,
                                                    uint16_t mask) {
    asm volatile(
        "cp.async.bulk.shared::cluster.global.mbarrier::complete_tx::bytes.multicast::cluster "
        "[%0], [%1], %2, [%3], %4;"
        :: "r"(dst), "l"(src), "r"(bytes), "r"(mbar), "h"(mask) : "memory");
}
static __device__ __forceinline__ void expect_tx(uint32_t mbar, uint32_t bytes) {
    asm volatile("mbarrier.arrive.expect_tx.shared.b64 _, [%0], %1;"
                 :: "r"(mbar), "r"(bytes) : "memory");
}
static __device__ __forceinline__ void tc_commit(uint32_t mbar) {
    asm volatile("tcgen05.commit.cta_group::1.mbarrier::arrive::one.shared::cluster.b64 [%0];"
                 :: "r"(mbar) : "memory");
}
static __device__ __forceinline__ void cluster_sync_all() {
    asm volatile("barrier.cluster.arrive.aligned;" ::: "memory");
    asm volatile("barrier.cluster.wait.aligned;"  ::: "memory");
}

#define LDTM16(r, addr) asm volatile( \
    "tcgen05.ld.sync.aligned.32x32b.x16.b32 " \
    "{%0,%1,%2,%3,%4,%5,%6,%7,%8,%9,%10,%11,%12,%13,%14,%15}, [%16];" \
    : "=r"(r[0]),"=r"(r[1]),"=r"(r[2]),"=r"(r[3]),"=r"(r[4]),"=r"(r[5]),"=r"(r[6]),"=r"(r[7]), \
      "=r"(r[8]),"=r"(r[9]),"=r"(r[10]),"=r"(r[11]),"=r"(r[12]),"=r"(r[13]),"=r"(r[14]),"=r"(r[15]) \
    : "r"(addr))

#define STTM8(addr, r) asm volatile( \
    "tcgen05.st.sync.aligned.32x32b.x8.b32 [%0], {%1,%2,%3,%4,%5,%6,%7,%8};" \
    :: "r"(addr), "r"((r)[0]),"r"((r)[1]),"r"((r)[2]),"r"((r)[3]), \
       "r"((r)[4]),"r"((r)[5]),"r"((r)[6]),"r"((r)[7]) : "memory")

#define LDTM32(r, addr) asm volatile( \
    "tcgen05.ld.sync.aligned.32x32b.x32.b32 " \
    "{%0,%1,%2,%3,%4,%5,%6,%7,%8,%9,%10,%11,%12,%13,%14,%15," \
    "%16,%17,%18,%19,%20,%21,%22,%23,%24,%25,%26,%27,%28,%29,%30,%31}, [%32];" \
    : "=r"(r[0]),"=r"(r[1]),"=r"(r[2]),"=r"(r[3]),"=r"(r[4]),"=r"(r[5]),"=r"(r[6]),"=r"(r[7]), \
      "=r"(r[8]),"=r"(r[9]),"=r"(r[10]),"=r"(r[11]),"=r"(r[12]),"=r"(r[13]),"=r"(r[14]),"=r"(r[15]), \
      "=r"(r[16]),"=r"(r[17]),"=r"(r[18]),"=r"(r[19]),"=r"(r[20]),"=r"(r[21]),"=r"(r[22]),"=r"(r[23]), \
      "=r"(r[24]),"=r"(r[25]),"=r"(r[26]),"=r"(r[27]),"=r"(r[28]),"=r"(r[29]),"=r"(r[30]),"=r"(r[31]) \
    : "r"(addr))
#endif  // TC_OK

__global__ __launch_bounds__(THREADS, 1) __cluster_dims__(1, 2, 1)
void ffq_tc_kernel(const float* __restrict__ x,
                   const float* __restrict__ qp,
                   float* __restrict__ out)
{
#if TC_OK
    extern __shared__ char smem[];
    const uint32_t sbase = smem_u32(smem);
    const int tid = threadIdx.x;
    const int w = tid >> 5, lane = tid & 31;
    const int nb = blockIdx.x;
    const int bm = blockIdx.y * BM;
    const int bn = nb * BN;
    const uint32_t rank = cl_rank();       // 0 or 1 within cluster
    const uint32_t peer = rank ^ 1;

    const uint32_t M1D = sbase + OFF_M1D;
    const uint32_t CV  = sbase + OFF_CV;
    const uint32_t MD  = sbase + OFF_MD;
    const uint32_t BF  = sbase + OFF_BF;
    const uint32_t W1F = sbase + OFF_W1F;
    const uint32_t RC  = sbase + OFF_RC;
    const uint32_t RW  = sbase + OFF_RW;
    const unsigned char* bsrc = g_w2conv + (size_t)nb * NCHUNK * B_SLOT;

    if (w == 0) {
        asm volatile("tcgen05.alloc.cta_group::1.sync.aligned.shared::cta.b32 [%0], %1;"
                     :: "r"(sbase + OFF_TMEM), "r"(512) : "memory");
        asm volatile("tcgen05.relinquish_alloc_permit.cta_group::1.sync.aligned;");
        if (elect_one()) {
#pragma unroll
            for (int i = 0; i < 2; ++i) {
                asm volatile("mbarrier.init.shared.b64 [%0], %1;" :: "r"(M1D + 8*i), "r"(1u)  : "memory");
                asm volatile("mbarrier.init.shared.b64 [%0], %1;" :: "r"(CV  + 8*i), "r"(16u) : "memory");
                asm volatile("mbarrier.init.shared.b64 [%0], %1;" :: "r"(MD  + 8*i), "r"(1u)  : "memory");
            }
#pragma unroll
            for (int i = 0; i < 5; ++i) {
                asm volatile("mbarrier.init.shared.b64 [%0], %1;" :: "r"(BF + 8*i), "r"(1u) : "memory");
                asm volatile("mbarrier.init.shared.b64 [%0], %1;" :: "r"(RC + 8*i), "r"(2u) : "memory");
            }
#pragma unroll
            for (int i = 0; i < 4; ++i) {
                asm volatile("mbarrier.init.shared.b64 [%0], %1;" :: "r"(W1F + 8*i), "r"(1u) : "memory");
                asm volatile("mbarrier.init.shared.b64 [%0], %1;" :: "r"(RW + 8*i),  "r"(2u) : "memory");
            }
        }
    }

    // Q staging: thread t<128 computes row bm+t quantum features -> fp16 SW128
    if (tid < 128) {
        const int m = bm + tid;
        float c[NQ];
#pragma unroll
        for (int j = 0; j < NQ; j++) c[j] = cosf(x[m * NQ + j] + qp[j]);
        float suf = 1.0f;
#pragma unroll
        for (int j = 1; j < NQ; j++) suf *= c[j];
        float qv[NQ];
        qv[0] = suf;
        float pre = c[0];
#pragma unroll
        for (int j = 1; j < NQ; j++) { pre *= c[j]; qv[j] = pre; }
        uint32_t u0 = pack_f16(qv[0], qv[1]);
        uint32_t u1 = pack_f16(qv[2], qv[3]);
        uint32_t u2 = pack_f16(qv[4], qv[5]);
        uint32_t u3 = pack_f16(qv[6], qv[7]);
        uint32_t u4 = pack_f16(qv[8], qv[9]);
        char* qb = smem + OFF_Q;
        *(uint4*)(qb + SW128((uint32_t)(tid * 128)))      = make_uint4(u0, u1, u2, u3);
        *(uint4*)(qb + SW128((uint32_t)(tid * 128 + 16))) = make_uint4(u4, 0, 0, 0);
#pragma unroll
        for (int g = 2; g < 8; ++g)
            *(uint4*)(qb + SW128((uint32_t)(tid * 128 + g * 16))) = make_uint4(0, 0, 0, 0);
    }
    __syncthreads();
    asm volatile("fence.proxy.async.shared::cta;" ::: "memory");

    // all barriers initialized in both CTAs before any multicast
    cluster_sync_all();

    int rcph[5] = {0,0,0,0,0};
    int rwph[4] = {0,0,0,0};

    // prologue copies (cooperative-sliced multicast)
    if (w == 1 && lane == 0) {
#pragma unroll
        for (int s = 0; s < 5; ++s) {
            expect_tx(BF + 8*s, B_SLOT);
            mbar_arrive(RC + 8*s);
            mbar_arrive_remote(RC + 8*s, peer);
            mbar_wait(RC + 8*s, 0); rcph[s] = 1;
            bulk_copy_mc(sbase + OFF_B + s * B_SLOT + rank * 16384,
                         bsrc + (size_t)s * B_SLOT + rank * 16384,
                         16384, BF + 8*s, 3);
        }
    }
    if (w == 2 && lane == 0) {
#pragma unroll
        for (int s = 0; s < 4; ++s) {
            expect_tx(W1F + 8*s, W1_SLOT);
            mbar_arrive(RW + 8*s);
            mbar_arrive_remote(RW + 8*s, peer);
            if (rank == 0) {
                mbar_wait(RW + 8*s, 0); rwph[s] = 1;
                bulk_copy_mc(sbase + OFF_W1S + s * W1_SLOT,
                             g_w1conv + (size_t)s * W1_SLOT, W1_SLOT, W1F + 8*s, 3);
            }
        }
    }

    uint32_t tmem_base;
    asm volatile("ld.shared.b32 %0, [%1];" : "=r"(tmem_base) : "r"(sbase + OFF_TMEM));
    const ull qdesc = make_desc(sbase + OFF_Q);

    if (w == 0) {
        // ===================== scheduler =====================
        if (elect_one()) {
            int cvc[2] = {0,0}, bfc[5] = {0,0,0,0,0}, w1c[4] = {0,0,0,0};
            // MMA1 for chunks 0,1
#pragma unroll
            for (int c0 = 0; c0 < 2; ++c0) {
                mbar_wait(W1F + 8*c0, 0); w1c[c0]++;
                mma_ss(tmem_base + TM_D2 + c0 * 64, qdesc,
                       make_desc(sbase + OFF_W1S + c0 * W1_SLOT), IDESC1, 0u);
                tc_commit(M1D + 8*c0);
            }
            for (int c = 0; c < NCHUNK; ++c) {
                const int pr = c & 1;
                mbar_wait(CV + 8*pr, cvc[pr] & 1); cvc[pr]++;
                asm volatile("tcgen05.fence::after_thread_sync;" ::: "memory");
                if (c + 2 < NCHUNK) {
                    const int s = (c + 2) & 3;
                    mbar_wait(W1F + 8*s, w1c[s] & 1); w1c[s]++;
                    mma_ss(tmem_base + TM_D2 + pr * 64, qdesc,
                           make_desc(sbase + OFF_W1S + s * W1_SLOT), IDESC1, 0u);
                    tc_commit(M1D + 8*pr);
                }
                const int bs = c % 5;
                mbar_wait(BF + 8*bs, bfc[bs] & 1); bfc[bs]++;
                const ull bD = make_desc(sbase + OFF_B + bs * B_SLOT);
                const uint32_t aT = tmem_base + TM_A + pr * 32;
#pragma unroll
                for (int ks = 0; ks < 4; ++ks)
                    mma_ts(tmem_base + TM_D, aT + ks * 8, bD + ks * 2, IDESC2,
                           (c > 0) || (ks > 0));
                tc_commit(MD + 8*pr);
            }
        }
    } else {
        // ===================== convert warps (1..16) =====================
        const int sp = w & 3;             // HW subpartition
        const int kq = (w - 1) >> 2;      // k-quarter 0..3
        int m1c[2] = {0,0}, mdc[2] = {0,0};

        for (int c = 0; c < NCHUNK; ++c) {
            const int pr = c & 1;
            if (c >= 2) {
                const int mp = (c - 2) & 1;
                mbar_wait(MD + 8*mp, mdc[mp] & 1); mdc[mp]++;
                // warp 1: B slot (c-2)%5 free locally -> ready-protocol for chunk c+3
                if (w == 1 && c + 3 < NCHUNK && lane == 0) {
                    const int cc = c + 3, s = cc % 5;
                    expect_tx(BF + 8*s, B_SLOT);
                    mbar_arrive(RC + 8*s);
                    mbar_arrive_remote(RC + 8*s, peer);
                    mbar_wait(RC + 8*s, rcph[s] & 1); rcph[s]++;
                    bulk_copy_mc(sbase + OFF_B + s * B_SLOT + rank * 16384,
                                 bsrc + (size_t)cc * B_SLOT + rank * 16384,
                                 16384, BF + 8*s, 3);
                }
            }
            mbar_wait(M1D + 8*pr, m1c[pr] & 1); m1c[pr]++;
            // warp 2: W1 slot c&3 free locally -> ready-protocol for chunk c+4
            if (w == 2 && c + 4 < NCHUNK && lane == 0) {
                const int cc = c + 4, s = cc & 3;
                expect_tx(W1F + 8*s, W1_SLOT);
                mbar_arrive(RW + 8*s);
                mbar_arrive_remote(RW + 8*s, peer);
                if (rank == 0) {
                    mbar_wait(RW + 8*s, rwph[s] & 1); rwph[s]++;
                    bulk_copy_mc(sbase + OFF_W1S + s * W1_SLOT,
                                 g_w1conv + (size_t)cc * W1_SLOT, W1_SLOT, W1F + 8*s, 3);
                }
            }
            asm volatile("tcgen05.fence::after_thread_sync;" ::: "memory");

            uint32_t r[16];
            LDTM16(r, tmem_base + TM_D2 + pr * 64 + kq * 16);
            asm volatile("tcgen05.wait::ld.sync.aligned;" ::: "memory");
            uint32_t h[8];
#pragma unroll
            for (int i = 0; i < 8; ++i) {
                float f0 = fmaxf(__uint_as_float(r[2*i]),     0.0f);
                float f1 = fmaxf(__uint_as_float(r[2*i + 1]), 0.0f);
                h[i] = pack_f16(f0, f1);
            }
            STTM8(tmem_base + TM_A + pr * 32 + kq * 8 + ((uint32_t)sp << 21), h);
            asm volatile("tcgen05.wait::st.sync.aligned;" ::: "memory");
            asm volatile("tcgen05.fence::before_thread_sync;" ::: "memory");
            if (elect_one()) mbar_arrive(CV + 8*pr);
        }

        // wait final MMA2 (chunk 63 -> MD[1])
        mbar_wait(MD + 8*1, mdc[1] & 1);
        asm volatile("tcgen05.fence::after_thread_sync;" ::: "memory");

        // epilogue: warp (sp,kq): rows sp*32+lane, cols kq*64..+63
        {
            const int m = bm + sp * 32 + lane;
            float* orow = out + (size_t)m * NDIM + bn + kq * 64;
#pragma unroll
            for (int q = 0; q < 2; ++q) {
                uint32_t r[32];
                LDTM32(r, tmem_base + TM_D + kq * 64 + q * 32);
                asm volatile("tcgen05.wait::ld.sync.aligned;" ::: "memory");
#pragma unroll
                for (int i = 0; i < 8; ++i) {
                    *(float4*)(orow + q * 32 + 4 * i) =
                        make_float4(__uint_as_float(r[4*i]),   __uint_as_float(r[4*i+1]),
                                    __uint_as_float(r[4*i+2]), __uint_as_float(r[4*i+3]));
                }
            }
        }
    }

    __syncthreads();
    // no CTA exits while a peer's multicast targeting its SMEM may be in flight
    cluster_sync_all();
    if (w == 0) {
        asm volatile("tcgen05.dealloc.cta_group::1.sync.aligned.b32 %0, %1;"
                     :: "r"(tmem_base), "r"(512));
    }
#endif  // TC_OK
}

// ============================================================================
// Kernel B: known-good FFMA fallback — active only WITHOUT SM103_ALL
// ============================================================================
#define FBM 128
#define FBN 128
#define FBK 16

__global__ __launch_bounds__(256)
void ffq_fused_kernel(const float* __restrict__ x,
                      const float* __restrict__ qp,
                      const float* __restrict__ W1,
                      const float* __restrict__ W2,
                      float* __restrict__ out)
{
#if !TC_OK
    __shared__ float qs[FBM][NQ];
    __shared__ float As[FBK][FBM];
    __shared__ float Bs[FBK][FBN];

    const int tid = threadIdx.x;
    const int bm  = blockIdx.y * FBM;
    const int bn  = blockIdx.x * FBN;

    if (tid < FBM) {
        const int r = bm + tid;
        float c[NQ];
#pragma unroll
        for (int j = 0; j < NQ; j++) c[j] = cosf(x[r * NQ + j] + qp[j]);
        float suf = 1.0f;
#pragma unroll
        for (int j = 1; j < NQ; j++) suf *= c[j];
        qs[tid][0] = suf;
        float pre = c[0];
#pragma unroll
        for (int j = 1; j < NQ; j++) { pre *= c[j]; qs[tid][j] = pre; }
    }
    __syncthreads();

    const int ty = tid >> 4, tx = tid & 15;
    const int a_m = tid >> 1, a_kh = (tid & 1) * 8;

    float acc[8][8];
#pragma unroll
    for (int i = 0; i < 8; i++)
#pragma unroll
        for (int j = 0; j < 8; j++) acc[i][j] = 0.0f;

    float qr[NQ];
#pragma unroll
    for (int j = 0; j < NQ; j++) qr[j] = qs[a_m][j];

    for (int kk = 0; kk < KDIM; kk += FBK) {
#pragma unroll
        for (int ki = 0; ki < 8; ki++) {
            const int k = a_kh + ki;
            const float* ww = &W1[(kk + k) * NQ];
            float s = 0.0f;
#pragma unroll
            for (int j = 0; j < NQ; j++) s += qr[j] * ww[j];
            As[k][a_m] = fmaxf(s, 0.0f);
        }
#pragma unroll
        for (int v = 0; v < 2; v++) {
            const int idx = tid + v * 256;
            const int nrow = idx >> 2, kc = (idx & 3) * 4;
            const float4 t = *(const float4*)&W2[(size_t)(bn + nrow) * KDIM + kk + kc];
            Bs[kc + 0][nrow] = t.x; Bs[kc + 1][nrow] = t.y;
            Bs[kc + 2][nrow] = t.z; Bs[kc + 3][nrow] = t.w;
        }
        __syncthreads();
#pragma unroll
        for (int k = 0; k < FBK; k++) {
            float a[8], b[8];
            const float4 a0 = *(const float4*)&As[k][ty * 8];
            const float4 a1 = *(const float4*)&As[k][ty * 8 + 4];
            const float4 b0 = *(const float4*)&Bs[k][tx * 8];
            const float4 b1 = *(const float4*)&Bs[k][tx * 8 + 4];
            a[0]=a0.x;a[1]=a0.y;a[2]=a0.z;a[3]=a0.w;a[4]=a1.x;a[5]=a1.y;a[6]=a1.z;a[7]=a1.w;
            b[0]=b0.x;b[1]=b0.y;b[2]=b0.z;b[3]=b0.w;b[4]=b1.x;b[5]=b1.y;b[6]=b1.z;b[7]=b1.w;
#pragma unroll
            for (int i = 0; i < 8; i++)
#pragma unroll
                for (int j = 0; j < 8; j++) acc[i][j] += a[i] * b[j];
        }
        __syncthreads();
    }
#pragma unroll
    for (int i = 0; i < 8; i++) {
        const int m = bm + ty * 8 + i;
        float* o = &out[(size_t)m * NDIM + bn + tx * 8];
        *(float4*)&o[0] = make_float4(acc[i][0], acc[i][1], acc[i][2], acc[i][3]);
        *(float4*)&o[4] = make_float4(acc[i][4], acc[i][5], acc[i][6], acc[i][7]);
    }
#endif  // !TC_OK
}

extern "C" void kernel_launch(void* const* d_in, const int* in_sizes, int n_in,
                              void* d_out, int out_size)
{
    const float* x  = (const float*)d_in[0];
    const float* qp = (const float*)d_in[1];
    const float* W1 = (const float*)d_in[2];
    const float* W2 = (const float*)d_in[3];
    float* out = (float*)d_out;

    const int M = in_sizes[0] / NQ;   // 16384

    cudaFuncAttributes fa; fa.numRegs = 0;
    cudaError_t qerr = cudaFuncGetAttributes(&fa, ffq_tc_kernel);
    const bool tc = (qerr == cudaSuccess) && (fa.numRegs > 32);

    if (tc || qerr != cudaSuccess) {
        convert_w2_kernel<<<(NDIM * KDIM / 8) / 256, 256>>>(W2);
        convert_w1_kernel<<<(NCHUNK * KC) / 256, 256>>>(W1);
        cudaFuncSetAttribute(ffq_tc_kernel, cudaFuncAttributeMaxDynamicSharedMemorySize, SMEM_BYTES);
        dim3 grid(NBLK, M / BM);      // (4, 128), clusters of 2 along y
        ffq_tc_kernel<<<grid, THREADS, SMEM_BYTES>>>(x, qp, out);
    }
    if (!tc) {
        dim3 gridB(NDIM / FBN, M / FBM);
        ffq_fused_kernel<<<gridB, 256>>>(x, qp, W1, W2, out);
    }
}

// round 14
// speedup vs baseline: 1.2473x; 1.2473x over previous
#include <cuda_runtime.h>
#include <cuda_fp16.h>
#include <math.h>
#include <stdint.h>

typedef unsigned long long ull;

#define NQ      10
#define KDIM    4096
#define NDIM    1024
#define BM      128
#define BN      256
#define KC      128
#define NCHUNK  32
#define THREADS 544
#define NBLK    (NDIM / BN)          // 4

#if defined(__CUDA_ARCH__) && defined(__CUDA_ARCH_HAS_FEATURE__)
#  if __CUDA_ARCH_HAS_FEATURE__(SM103_ALL) || __CUDA_ARCH_HAS_FEATURE__(SM100_ALL)
#    define TC_OK 1
#  endif
#endif
#ifndef TC_OK
#  define TC_OK 0
#endif

// control SMEM
#define OFF_TMEM 0
#define OFF_M1D  16                  // 2 x 8B mma1-done
#define OFF_CV   32                  // 2 x 8B convert-done (count 16)
#define OFF_MD   48                  // 2 x 8B mma2-done
#define OFF_BF   64                  // 3 x 8B B-slot-full
#define OFF_W1F  88                  // 1 x 8B W1-slot-full
#define OFF_Q    1024                // Q tile 16KB (128 x 128B SW128)
#define OFF_W1S  17408               // 1 x 16KB W1 fp16 tile
#define OFF_B    33792               // 3 x 64KB W2 fp16 tiles
#define B_SLOT   65536
#define W1_SLOT  16384
#define SMEM_BYTES (OFF_B + 3 * B_SLOT)   // 230400

// TMEM columns
#define TM_D   0                     // main accum, 256 cols
#define TM_D2  256                   // MMA1 out (single buf), 128 cols
#define TM_A   384                   // A operand, 2 x 64 cols

// idesc kind::f16 fp16 in, f32 accum
#define IDESC2 0x08400010u           // M=128, N=256
#define IDESC1 0x08200010u           // M=128, N=128
#define SW128(o) ((o) ^ (((o) >> 3) & 0x70))

// converted W2: [nb][chunk64] 32KB fp16 SW128 tiles (8MB); two adjacent = one 64KB KC=128 slot
__device__ __align__(1024) unsigned char g_w2conv[(size_t)NBLK * 64 * 32768];
// converted W1: [chunk128] 16KB fp16 SW128 tiles (128 rows(k) x 16 cols(j), padded)
__device__ __align__(1024) unsigned char g_w1conv[(size_t)NCHUNK * W1_SLOT];

static __device__ __forceinline__ uint32_t pack_f16(float lo, float hi) {
    uint32_t r;
    asm("cvt.rn.f16x2.f32 %0, %1, %2;" : "=r"(r) : "f"(hi), "f"(lo));
    return r;
}

// ============================================================================
// Kernel 0: W2 fp32 -> fp16 SW128 tiles (32KB per 64-k tile, contiguous pairs)
// ============================================================================
__global__ __launch_bounds__(256)
void convert_w2_kernel(const float* __restrict__ W2)
{
    const int t   = blockIdx.x * 256 + threadIdx.x;
    const int row = t >> 9;
    const int k0  = (t & 511) << 3;
    const int nb  = row >> 8, n = row & 255;
    const int c   = k0 >> 6,  k = k0 & 63;

    const float4* p = (const float4*)(W2 + (size_t)row * KDIM + k0);
    const float4 u = p[0], v = p[1];
    uint32_t h0 = pack_f16(u.x, u.y);
    uint32_t h1 = pack_f16(u.z, u.w);
    uint32_t h2 = pack_f16(v.x, v.y);
    uint32_t h3 = pack_f16(v.z, v.w);

    unsigned char* base = g_w2conv + ((size_t)(nb * 64 + c)) * 32768;
    const uint32_t off = SW128((uint32_t)(n * 128 + k * 2));
    *(uint4*)(base + off) = make_uint4(h0, h1, h2, h3);
}

// ============================================================================
// Kernel 1: W1 fp32 -> fp16 SW128 tiles (128 k-rows per KC=128 chunk)
// ============================================================================
__global__ __launch_bounds__(256)
void convert_w1_kernel(const float* __restrict__ W1)
{
    const int t = blockIdx.x * 256 + threadIdx.x;    // 4096 threads
    const int chunk = t >> 7, n = t & 127;

    const float* wr = W1 + (size_t)(chunk * KC + n) * NQ;
    uint32_t u0 = pack_f16(wr[0], wr[1]);
    uint32_t u1 = pack_f16(wr[2], wr[3]);
    uint32_t u2 = pack_f16(wr[4], wr[5]);
    uint32_t u3 = pack_f16(wr[6], wr[7]);
    uint32_t u4 = pack_f16(wr[8], wr[9]);

    unsigned char* base = g_w1conv + (size_t)chunk * W1_SLOT;
    *(uint4*)(base + SW128((uint32_t)(n * 128)))      = make_uint4(u0, u1, u2, u3);
    *(uint4*)(base + SW128((uint32_t)(n * 128 + 16))) = make_uint4(u4, 0, 0, 0);
#pragma unroll
    for (int g = 2; g < 8; ++g)
        *(uint4*)(base + SW128((uint32_t)(n * 128 + g * 16))) = make_uint4(0, 0, 0, 0);
}

// ============================================================================
// Kernel 2: tcgen05 double-GEMM, KC=128 chunks
// ============================================================================
#if TC_OK
static __device__ __forceinline__ uint32_t smem_u32(const void* p) {
    uint32_t a;
    asm("{ .reg .u64 t; cvta.to.shared.u64 t, %1; cvt.u32.u64 %0, t; }" : "=r"(a) : "l"(p));
    return a;
}
static __device__ __forceinline__ bool elect_one() {
    uint32_t p;
    asm volatile("{ .reg .pred P; elect.sync _|P, 0xFFFFFFFF; selp.b32 %0, 1, 0, P; }" : "=r"(p));
    return p != 0;
}
static __device__ __forceinline__ ull make_desc(uint32_t addr) {  // SW128 K-major
    return (2ULL << 61) | (1ULL << 46) | (64ULL << 32) | (1ULL << 16) |
           (ull)((addr >> 4) & 0x3FFF);
}
static __device__ __forceinline__ void mbar_wait(uint32_t mbar, uint32_t ph) {
    asm volatile(
        "{\n\t.reg .pred P;\n"
        "WL_%=:\n\t"
        "mbarrier.try_wait.parity.acquire.cta.shared::cta.b64 P, [%0], %1, 0x989680;\n\t"
        "@P bra WD_%=;\n\t"
        "bra WL_%=;\n"
        "WD_%=:\n\t}"
        :: "r"(mbar), "r"(ph) : "memory");
}
static __device__ __forceinline__ void mbar_arrive(uint32_t mbar) {
    asm volatile("mbarrier.arrive.shared.b64 _, [%0];" :: "r"(mbar) : "memory");
}
static __device__ __forceinline__ void mma_ss(uint32_t d, ull a, ull b, uint32_t idesc, uint32_t en) {
    asm volatile(
        "{\n\t.reg .pred p;\n\t"
        "setp.ne.u32 p, %5, 0;\n\t"
        "tcgen05.mma.cta_group::1.kind::f16 [%0], %1, %2, %3, {%4,%4,%4,%4}, p;\n\t}"
        :: "r"(d), "l"(a), "l"(b), "r"(idesc), "r"(0u), "r"(en) : "memory");
}
static __device__ __forceinline__ void mma_ts(uint32_t d, uint32_t a, ull b, uint32_t idesc, uint32_t en) {
    asm volatile(
        "{\n\t.reg .pred p;\n\t"
        "setp.ne.u32 p, %5, 0;\n\t"
        "tcgen05.mma.cta_group::1.kind::f16 [%0], [%1], %2, %3, {%4,%4,%4,%4}, p;\n\t}"
        :: "r"(d), "r"(a), "l"(b), "r"(idesc), "r"(0u), "r"(en) : "memory");
}
static __device__ __forceinline__ void bulk_copy(uint32_t dst, const void* src,
                                                 uint32_t bytes, uint32_t mbar) {
    asm volatile(
        "cp.async.bulk.shared::cluster.global.mbarrier::complete_tx::bytes [%0], [%1], %2, [%3];"
        :: "r"(dst), "l"(src), "r"(bytes), "r"(mbar) : "memory");
}
static __device__ __forceinline__ void expect_tx(uint32_t mbar, uint32_t bytes) {
    asm volatile("mbarrier.arrive.expect_tx.shared.b64 _, [%0], %1;"
                 :: "r"(mbar), "r"(bytes) : "memory");
}
static __device__ __forceinline__ void tc_commit(uint32_t mbar) {
    asm volatile("tcgen05.commit.cta_group::1.mbarrier::arrive::one.shared::cluster.b64 [%0];"
                 :: "r"(mbar) : "memory");
}

#define STTM16(addr, r) asm volatile( \
    "tcgen05.st.sync.aligned.32x32b.x16.b32 [%0], " \
    "{%1,%2,%3,%4,%5,%6,%7,%8,%9,%10,%11,%12,%13,%14,%15,%16};" \
    :: "r"(addr), \
       "r"((r)[0]),"r"((r)[1]),"r"((r)[2]),"r"((r)[3]), \
       "r"((r)[4]),"r"((r)[5]),"r"((r)[6]),"r"((r)[7]), \
       "r"((r)[8]),"r"((r)[9]),"r"((r)[10]),"r"((r)[11]), \
       "r"((r)[12]),"r"((r)[13]),"r"((r)[14]),"r"((r)[15]) : "memory")

#define LDTM32(r, addr) asm volatile( \
    "tcgen05.ld.sync.aligned.32x32b.x32.b32 " \
    "{%0,%1,%2,%3,%4,%5,%6,%7,%8,%9,%10,%11,%12,%13,%14,%15," \
    "%16,%17,%18,%19,%20,%21,%22,%23,%24,%25,%26,%27,%28,%29,%30,%31}, [%32];" \
    : "=r"(r[0]),"=r"(r[1]),"=r"(r[2]),"=r"(r[3]),"=r"(r[4]),"=r"(r[5]),"=r"(r[6]),"=r"(r[7]), \
      "=r"(r[8]),"=r"(r[9]),"=r"(r[10]),"=r"(r[11]),"=r"(r[12]),"=r"(r[13]),"=r"(r[14]),"=r"(r[15]), \
      "=r"(r[16]),"=r"(r[17]),"=r"(r[18]),"=r"(r[19]),"=r"(r[20]),"=r"(r[21]),"=r"(r[22]),"=r"(r[23]), \
      "=r"(r[24]),"=r"(r[25]),"=r"(r[26]),"=r"(r[27]),"=r"(r[28]),"=r"(r[29]),"=r"(r[30]),"=r"(r[31]) \
    : "r"(addr))
#endif  // TC_OK

__global__ __launch_bounds__(THREADS, 1)
void ffq_tc_kernel(const float* __restrict__ x,
                   const float* __restrict__ qp,
                   float* __restrict__ out)
{
#if TC_OK
    extern __shared__ char smem[];
    const uint32_t sbase = smem_u32(smem);
    const int tid = threadIdx.x;
    const int w = tid >> 5, lane = tid & 31;
    const int nb = blockIdx.x;
    const int bm = blockIdx.y * BM;
    const int bn = nb * BN;

    const uint32_t M1D = sbase + OFF_M1D;
    const uint32_t CV  = sbase + OFF_CV;
    const uint32_t MD  = sbase + OFF_MD;
    const uint32_t BF  = sbase + OFF_BF;
    const uint32_t W1F = sbase + OFF_W1F;
    const unsigned char* bsrc = g_w2conv + (size_t)nb * 64 * 32768;

    if (w == 0) {
        asm volatile("tcgen05.alloc.cta_group::1.sync.aligned.shared::cta.b32 [%0], %1;"
                     :: "r"(sbase + OFF_TMEM), "r"(512) : "memory");
        asm volatile("tcgen05.relinquish_alloc_permit.cta_group::1.sync.aligned;");
        if (elect_one()) {
#pragma unroll
            for (int i = 0; i < 2; ++i) {
                asm volatile("mbarrier.init.shared.b64 [%0], %1;" :: "r"(M1D + 8*i), "r"(1u)  : "memory");
                asm volatile("mbarrier.init.shared.b64 [%0], %1;" :: "r"(CV  + 8*i), "r"(16u) : "memory");
                asm volatile("mbarrier.init.shared.b64 [%0], %1;" :: "r"(MD  + 8*i), "r"(1u)  : "memory");
            }
#pragma unroll
            for (int i = 0; i < 3; ++i)
                asm volatile("mbarrier.init.shared.b64 [%0], %1;" :: "r"(BF + 8*i), "r"(1u) : "memory");
            asm volatile("mbarrier.init.shared.b64 [%0], %1;" :: "r"(W1F), "r"(1u) : "memory");
        }
    }

    // Q staging: thread t<128 computes row bm+t quantum features -> fp16 SW128
    if (tid < 128) {
        const int m = bm + tid;
        float c[NQ];
#pragma unroll
        for (int j = 0; j < NQ; j++) c[j] = cosf(x[m * NQ + j] + qp[j]);
        float suf = 1.0f;
#pragma unroll
        for (int j = 1; j < NQ; j++) suf *= c[j];
        float qv[NQ];
        qv[0] = suf;
        float pre = c[0];
#pragma unroll
        for (int j = 1; j < NQ; j++) { pre *= c[j]; qv[j] = pre; }
        uint32_t u0 = pack_f16(qv[0], qv[1]);
        uint32_t u1 = pack_f16(qv[2], qv[3]);
        uint32_t u2 = pack_f16(qv[4], qv[5]);
        uint32_t u3 = pack_f16(qv[6], qv[7]);
        uint32_t u4 = pack_f16(qv[8], qv[9]);
        char* qb = smem + OFF_Q;
        *(uint4*)(qb + SW128((uint32_t)(tid * 128)))      = make_uint4(u0, u1, u2, u3);
        *(uint4*)(qb + SW128((uint32_t)(tid * 128 + 16))) = make_uint4(u4, 0, 0, 0);
#pragma unroll
        for (int g = 2; g < 8; ++g)
            *(uint4*)(qb + SW128((uint32_t)(tid * 128 + g * 16))) = make_uint4(0, 0, 0, 0);
    }
    __syncthreads();
    asm volatile("fence.proxy.async.shared::cta;" ::: "memory");

    // prologue copies: B chunks 0,1 (64KB each) and W1 chunk 0
    if (w == 1 && elect_one()) {
#pragma unroll
        for (int s = 0; s < 2; ++s) {
            expect_tx(BF + 8*s, B_SLOT);
            bulk_copy(sbase + OFF_B + s * B_SLOT, bsrc + (size_t)s * B_SLOT, B_SLOT, BF + 8*s);
        }
    }
    if (w == 2 && elect_one()) {
        expect_tx(W1F, W1_SLOT);
        bulk_copy(sbase + OFF_W1S, g_w1conv, W1_SLOT, W1F);
    }

    uint32_t tmem_base;
    asm volatile("ld.shared.b32 %0, [%1];" : "=r"(tmem_base) : "r"(sbase + OFF_TMEM));
    const ull qdesc = make_desc(sbase + OFF_Q);

    if (w == 0) {
        // ===================== scheduler =====================
        if (elect_one()) {
            int cvc[2] = {0,0}, bfc[3] = {0,0,0}, w1c = 0;
            // MMA1 for chunk 0
            mbar_wait(W1F, 0); w1c = 1;
            mma_ss(tmem_base + TM_D2, qdesc, make_desc(sbase + OFF_W1S), IDESC1, 0u);
            tc_commit(M1D + 0);
            for (int c = 0; c < NCHUNK; ++c) {
                const int pr = c & 1;
                mbar_wait(CV + 8*pr, cvc[pr] & 1); cvc[pr]++;
                asm volatile("tcgen05.fence::after_thread_sync;" ::: "memory");
                if (c + 1 < NCHUNK) {
                    mbar_wait(W1F, w1c & 1); w1c++;
                    mma_ss(tmem_base + TM_D2, qdesc, make_desc(sbase + OFF_W1S), IDESC1, 0u);
                    tc_commit(M1D + 8*((c + 1) & 1));
                }
                const int bs = c % 3;
                mbar_wait(BF + 8*bs, bfc[bs] & 1); bfc[bs]++;
                const ull bD = make_desc(sbase + OFF_B + bs * B_SLOT);
                const uint32_t aT = tmem_base + TM_A + pr * 64;
#pragma unroll
                for (int ks = 0; ks < 8; ++ks) {
                    const ull bd = bD + (ks >> 2) * 2048 + (ks & 3) * 2;
                    mma_ts(tmem_base + TM_D, aT + ks * 8, bd, IDESC2,
                           (c > 0) || (ks > 0));
                }
                tc_commit(MD + 8*pr);
            }
        }
    } else {
        // ===================== convert warps (1..16) =====================
        const int sp = w & 3;             // HW subpartition
        const int kq = (w - 1) >> 2;      // 32-col quarter of D2
        int m1c[2] = {0,0}, mdc[2] = {0,0};

        for (int c = 0; c < NCHUNK; ++c) {
            const int pr = c & 1;
            if (c >= 2) {
                const int mp = (c - 2) & 1;
                mbar_wait(MD + 8*mp, mdc[mp] & 1); mdc[mp]++;
            }
            // warp 1: B copy for chunk c+1 (slot (c+1)%3 freed by MD(c-2); virgin at c=1)
            if (w == 1 && c >= 1 && c + 1 < NCHUNK && elect_one()) {
                const int cc = c + 1, s = cc % 3;
                expect_tx(BF + 8*s, B_SLOT);
                bulk_copy(sbase + OFF_B + s * B_SLOT, bsrc + (size_t)cc * B_SLOT,
                          B_SLOT, BF + 8*s);
            }
            mbar_wait(M1D + 8*pr, m1c[pr] & 1); m1c[pr]++;
            // warp 2: W1 copy for chunk c+1 (slot freed by MMA1(c) completion = M1D(c))
            if (w == 2 && c + 1 < NCHUNK && elect_one()) {
                expect_tx(W1F, W1_SLOT);
                bulk_copy(sbase + OFF_W1S, g_w1conv + (size_t)(c + 1) * W1_SLOT,
                          W1_SLOT, W1F);
            }
            asm volatile("tcgen05.fence::after_thread_sync;" ::: "memory");

            uint32_t r[32];
            LDTM32(r, tmem_base + TM_D2 + kq * 32);
            asm volatile("tcgen05.wait::ld.sync.aligned;" ::: "memory");
            uint32_t h[16];
#pragma unroll
            for (int i = 0; i < 16; ++i) {
                float f0 = fmaxf(__uint_as_float(r[2*i]),     0.0f);
                float f1 = fmaxf(__uint_as_float(r[2*i + 1]), 0.0f);
                h[i] = pack_f16(f0, f1);
            }
            STTM16(tmem_base + TM_A + pr * 64 + kq * 16 + ((uint32_t)sp << 21), h);
            asm volatile("tcgen05.wait::st.sync.aligned;" ::: "memory");
            asm volatile("tcgen05.fence::before_thread_sync;" ::: "memory");
            if (elect_one()) mbar_arrive(CV + 8*pr);
        }

        // final MMA2 (chunk 31 -> MD[1], phase mdc[1])
        mbar_wait(MD + 8*1, mdc[1] & 1);
        asm volatile("tcgen05.fence::after_thread_sync;" ::: "memory");

        // epilogue: warp (sp,kq): rows sp*32+lane, cols kq*64..+63
        {
            const int m = bm + sp * 32 + lane;
            float* orow = out + (size_t)m * NDIM + bn + kq * 64;
#pragma unroll
            for (int q = 0; q < 2; ++q) {
                uint32_t r[32];
                LDTM32(r, tmem_base + TM_D + kq * 64 + q * 32);
                asm volatile("tcgen05.wait::ld.sync.aligned;" ::: "memory");
#pragma unroll
                for (int i = 0; i < 8; ++i) {
                    *(float4*)(orow + q * 32 + 4 * i) =
                        make_float4(__uint_as_float(r[4*i]),   __uint_as_float(r[4*i+1]),
                                    __uint_as_float(r[4*i+2]), __uint_as_float(r[4*i+3]));
                }
            }
        }
    }

    __syncthreads();
    if (w == 0) {
        asm volatile("tcgen05.dealloc.cta_group::1.sync.aligned.b32 %0, %1;"
                     :: "r"(tmem_base), "r"(512));
    }
#endif  // TC_OK
}

// ============================================================================
// Kernel B: known-good FFMA fallback — active only WITHOUT SM103_ALL
// ============================================================================
#define FBM 128
#define FBN 128
#define FBK 16

__global__ __launch_bounds__(256)
void ffq_fused_kernel(const float* __restrict__ x,
                      const float* __restrict__ qp,
                      const float* __restrict__ W1,
                      const float* __restrict__ W2,
                      float* __restrict__ out)
{
#if !TC_OK
    __shared__ float qs[FBM][NQ];
    __shared__ float As[FBK][FBM];
    __shared__ float Bs[FBK][FBN];

    const int tid = threadIdx.x;
    const int bm  = blockIdx.y * FBM;
    const int bn  = blockIdx.x * FBN;

    if (tid < FBM) {
        const int r = bm + tid;
        float c[NQ];
#pragma unroll
        for (int j = 0; j < NQ; j++) c[j] = cosf(x[r * NQ + j] + qp[j]);
        float suf = 1.0f;
#pragma unroll
        for (int j = 1; j < NQ; j++) suf *= c[j];
        qs[tid][0] = suf;
        float pre = c[0];
#pragma unroll
        for (int j = 1; j < NQ; j++) { pre *= c[j]; qs[tid][j] = pre; }
    }
    __syncthreads();

    const int ty = tid >> 4, tx = tid & 15;
    const int a_m = tid >> 1, a_kh = (tid & 1) * 8;

    float acc[8][8];
#pragma unroll
    for (int i = 0; i < 8; i++)
#pragma unroll
        for (int j = 0; j < 8; j++) acc[i][j] = 0.0f;

    float qr[NQ];
#pragma unroll
    for (int j = 0; j < NQ; j++) qr[j] = qs[a_m][j];

    for (int kk = 0; kk < KDIM; kk += FBK) {
#pragma unroll
        for (int ki = 0; ki < 8; ki++) {
            const int k = a_kh + ki;
            const float* ww = &W1[(kk + k) * NQ];
            float s = 0.0f;
#pragma unroll
            for (int j = 0; j < NQ; j++) s += qr[j] * ww[j];
            As[k][a_m] = fmaxf(s, 0.0f);
        }
#pragma unroll
        for (int v = 0; v < 2; v++) {
            const int idx = tid + v * 256;
            const int nrow = idx >> 2, kc = (idx & 3) * 4;
            const float4 t = *(const float4*)&W2[(size_t)(bn + nrow) * KDIM + kk + kc];
            Bs[kc + 0][nrow] = t.x; Bs[kc + 1][nrow] = t.y;
            Bs[kc + 2][nrow] = t.z; Bs[kc + 3][nrow] = t.w;
        }
        __syncthreads();
#pragma unroll
        for (int k = 0; k < FBK; k++) {
            float a[8], b[8];
            const float4 a0 = *(const float4*)&As[k][ty * 8];
            const float4 a1 = *(const float4*)&As[k][ty * 8 + 4];
            const float4 b0 = *(const float4*)&Bs[k][tx * 8];
            const float4 b1 = *(const float4*)&Bs[k][tx * 8 + 4];
            a[0]=a0.x;a[1]=a0.y;a[2]=a0.z;a[3]=a0.w;a[4]=a1.x;a[5]=a1.y;a[6]=a1.z;a[7]=a1.w;
            b[0]=b0.x;b[1]=b0.y;b[2]=b0.z;b[3]=b0.w;b[4]=b1.x;b[5]=b1.y;b[6]=b1.z;b[7]=b1.w;
#pragma unroll
            for (int i = 0; i < 8; i++)
#pragma unroll
                for (int j = 0; j < 8; j++) acc[i][j] += a[i] * b[j];
        }
        __syncthreads();
    }
#pragma unroll
    for (int i = 0; i < 8; i++) {
        const int m = bm + ty * 8 + i;
        float* o = &out[(size_t)m * NDIM + bn + tx * 8];
        *(float4*)&o[0] = make_float4(acc[i][0], acc[i][1], acc[i][2], acc[i][3]);
        *(float4*)&o[4] = make_float4(acc[i][4], acc[i][5], acc[i][6], acc[i][7]);
    }
#endif  // !TC_OK
}

extern "C" void kernel_launch(void* const* d_in, const int* in_sizes, int n_in,
                              void* d_out, int out_size)
{
    const float* x  = (const float*)d_in[0];
    const float* qp = (const float*)d_in[1];
    const float* W1 = (const float*)d_in[2];
    const float* W2 = (const float*)d_in[3];
    float* out = (float*)d_out;

    const int M = in_sizes[0] / NQ;   // 16384

    cudaFuncAttributes fa; fa.numRegs = 0;
    cudaError_t qerr = cudaFuncGetAttributes(&fa, ffq_tc_kernel);
    const bool tc = (qerr == cudaSuccess) && (fa.numRegs > 32);

    if (tc || qerr != cudaSuccess) {
        convert_w2_kernel<<<(NDIM * KDIM / 8) / 256, 256>>>(W2);
        convert_w1_kernel<<<(NCHUNK * KC) / 256, 256>>>(W1);
        cudaFuncSetAttribute(ffq_tc_kernel, cudaFuncAttributeMaxDynamicSharedMemorySize, SMEM_BYTES);
        dim3 grid(NBLK, M / BM);      // (4, 128)
        ffq_tc_kernel<<<grid, THREADS, SMEM_BYTES>>>(x, qp, out);
    }
    if (!tc) {
        dim3 gridB(NDIM / FBN, M / FBM);
        ffq_fused_kernel<<<gridB, 256>>>(x, qp, W1, W2, out);
    }
}